// round 9
// baseline (speedup 1.0000x reference)
#include <cuda_runtime.h>
#include <math.h>
#include <cstdint>

// Problem constants
#define NBLK 512
#define BQ   32
#define HH   16
#define DD   576
#define DD4  144
#define DVV  512
#define BSS  128
#define QSCALE 0.07216878364870322f  // 192^-0.5

typedef unsigned long long ull;

// Scratch (device globals — no allocation allowed)
__device__ float g_oacc[NBLK * HH * DVV];
__device__ float g_bm[NBLK * HH];
__device__ float g_bs[NBLK * HH];

// ---------------- helpers ----------------
__device__ __forceinline__ uint32_t smem_u32(const void* p) {
    uint32_t a;
    asm("{ .reg .u64 t; cvta.to.shared.u64 t, %1; cvt.u32.u64 %0, t; }" : "=r"(a) : "l"(p));
    return a;
}
__device__ __forceinline__ void cp16(uint32_t dst, const void* src) {
    asm volatile("cp.async.cg.shared.global [%0], [%1], 16;" :: "r"(dst), "l"(src));
}
#define CP_COMMIT() asm volatile("cp.async.commit_group;" ::: "memory")
#define CP_WAIT(n)  asm volatile("cp.async.wait_group %0;" :: "n"(n) : "memory")

__device__ __forceinline__ void fma2(ull& d, ull a, ull b) {
    asm("fma.rn.f32x2 %0, %1, %2, %0;" : "+l"(d) : "l"(a), "l"(b));
}
__device__ __forceinline__ float lo_f(ull v) { return __uint_as_float((unsigned)v); }
__device__ __forceinline__ float hi_f(ull v) { return __uint_as_float((unsigned)(v >> 32)); }
__device__ __forceinline__ ull dup2(float v) {
    unsigned u = __float_as_uint(v);
    return ((ull)u << 32) | u;
}

// ---------------- SMEM layout (bytes) ----------------
// K/V tiles : 3 x (16 rows x 145 f4) = 3 x 37120 = 111360   [0, 111360)
// q         : 16 rows x 145 f4 = 37120                      [111360, 148480)
// parts     : 256 cells x 17 floats = 17408                 [148480, 165888)
// pp        : 16 x 17 floats = 1088                         [165888, 166976)
// Mx/Lx/rr  : 3 x 16 floats                                 [166976, 167168)
#define TSTR 145
#define TILEB 37120
#define QOFF  111360
#define PARTOFF 148480
#define PPOFF 165888
#define MOFF  166976
#define LOFF  167040
#define RROFF 167104
#define SMEM_BYTES 167168

__global__ __launch_bounds__(256, 1) void mla_fused_kernel(
    const float* __restrict__ query,
    const float* __restrict__ key_cache,
    const float* __restrict__ block_bias,
    const int* __restrict__ block_list,
    const int* __restrict__ block_groups)
{
    extern __shared__ char smem[];
    const uint32_t sbase = smem_u32(smem);
    const int t = threadIdx.x;
    const int n = blockIdx.x;
    const int b = block_groups[n];
    const float4* kvb4 = (const float4*)(key_cache + (long)block_list[n] * (BSS * DD));
    const float4* q4 = (const float4*)query;

    const float4* qs4  = (const float4*)(smem + QOFF);
    float* parts = (float*)(smem + PARTOFF);
    float* pp    = (float*)(smem + PPOFF);
    float* Mx    = (float*)(smem + MOFF);
    float* Lx    = (float*)(smem + LOFF);
    float* rr    = (float*)(smem + RROFF);

    if (t < 16) { Mx[t] = -3e38f; Lx[t] = 0.f; }

    // ---- issue Q load (group 0): 2304 f4, padded rows
    #pragma unroll
    for (int j = 0; j < 9; j++) {
        int idx = t + j * 256;
        int row = idx / 144, col = idx - row * 144;
        cp16(sbase + QOFF + (unsigned)(row * TSTR + col) * 16,
             q4 + (long)(b * HH + row) * DD4 + col);
    }
    CP_COMMIT();

    // ---- tile loader: 16 rows x 144 f4 into buffer tl%3
    auto issueT = [&](int tl) {
        uint32_t tb = sbase + (unsigned)(tl % 3) * TILEB;
        #pragma unroll
        for (int j = 0; j < 9; j++) {
            int idx = t + j * 256;
            int row = idx / 144, col = idx - row * 144;
            cp16(tb + (unsigned)(row * TSTR + col) * 16,
                 kvb4 + (long)(tl * 16 + row) * DD4 + col);
        }
        CP_COMMIT();
    };
    issueT(0); issueT(1); issueT(2);

    // QK mapping: 16 d-groups of 36 d (9 f4). Warp covers g and g+4
    // (delta-kk 36 f4 = 144 words ≡ 16 mod 32 → clean banks vs hq/sq spread).
    const int wid  = t >> 5;
    const int half = (t >> 4) & 1;
    const int u    = t & 15;
    const int hq   = u & 3;     // h = hq + 4i
    const int squ  = u >> 2;    // s = squ + 4j
    const int g    = (wid & 3) + ((wid >> 2) << 3) + (half << 2);
    const int kbase = g * 9;

    // PV mapping: h = hb + 4i; v f4 cols {vb, vb+64}
    const int hb = t & 3;
    const int vb = t >> 2;      // 0..63

    ull o2[4][4];
    #pragma unroll
    for (int i = 0; i < 4; i++)
        #pragma unroll
        for (int k = 0; k < 4; k++) o2[i][k] = 0ull;

    for (int tl = 0; tl < 8; tl++) {
        if (tl < 6) { CP_WAIT(2); } else if (tl == 6) { CP_WAIT(1); } else { CP_WAIT(0); }
        __syncthreads();
        const float4* kt = (const float4*)(smem + (tl % 3) * TILEB);

        // ---- QK partials: 4h x 4s over d-range [g*36, g*36+36)
        {
            ull acc[4][4];
            #pragma unroll
            for (int i = 0; i < 4; i++)
                #pragma unroll
                for (int j = 0; j < 4; j++) acc[i][j] = 0ull;

            #pragma unroll
            for (int k4 = 0; k4 < 9; k4++) {
                ull qp[4][2], kp[4][2];
                #pragma unroll
                for (int i = 0; i < 4; i++) {
                    ulonglong2 qq = *(const ulonglong2*)&qs4[(hq + 4 * i) * TSTR + kbase + k4];
                    qp[i][0] = qq.x; qp[i][1] = qq.y;
                }
                #pragma unroll
                for (int j = 0; j < 4; j++) {
                    ulonglong2 kk = *(const ulonglong2*)&kt[(squ + 4 * j) * TSTR + kbase + k4];
                    kp[j][0] = kk.x; kp[j][1] = kk.y;
                }
                #pragma unroll
                for (int i = 0; i < 4; i++)
                    #pragma unroll
                    for (int j = 0; j < 4; j++) {
                        fma2(acc[i][j], qp[i][0], kp[j][0]);
                        fma2(acc[i][j], qp[i][1], kp[j][1]);
                    }
            }
            #pragma unroll
            for (int i = 0; i < 4; i++)
                #pragma unroll
                for (int j = 0; j < 4; j++) {
                    int cell = (hq + 4 * i) * 16 + squ + 4 * j;
                    parts[cell * 17 + g] = lo_f(acc[i][j]) + hi_f(acc[i][j]);
                }
        }
        __syncthreads();   // b1: all partials visible

        // ---- reduce + online softmax (warps 0..3; warp w owns rows 4w..4w+3)
        if (wid < 4) {
            int l  = t & 31;
            int h  = (wid << 2) + (l >> 3);
            int sl = l & 7;
            int s0 = 2 * sl, s1 = s0 + 1;
            float a0 = 0.f, a1 = 0.f;
            #pragma unroll
            for (int gg = 0; gg < 16; gg++) {
                a0 += parts[(h * 16 + s0) * 17 + gg];
                a1 += parts[(h * 16 + s1) * 17 + gg];
            }
            float sc0 = a0 * QSCALE + block_bias[n * BSS + tl * 16 + s0];
            float sc1 = a1 * QSCALE + block_bias[n * BSS + tl * 16 + s1];
            float tm = fmaxf(sc0, sc1);
            #pragma unroll
            for (int o = 4; o >= 1; o >>= 1)
                tm = fmaxf(tm, __shfl_xor_sync(0xffffffffu, tm, o));
            float Mo = Mx[h];
            float Mn = fmaxf(Mo, tm);
            float r  = __expf(Mo - Mn);
            float p0 = __expf(sc0 - Mn);
            float p1 = __expf(sc1 - Mn);
            pp[h * 17 + s0] = p0;
            pp[h * 17 + s1] = p1;
            float ps = p0 + p1;
            #pragma unroll
            for (int o = 4; o >= 1; o >>= 1)
                ps += __shfl_xor_sync(0xffffffffu, ps, o);
            if (sl == 0) {
                Lx[h] = Lx[h] * r + ps;
                Mx[h] = Mn;
                rr[h] = r;
            }
        }
        __syncthreads();   // b2: pp/rr ready

        // ---- PV: rescale o, accumulate this tile's 16 s-rows
        #pragma unroll
        for (int i = 0; i < 4; i++) {
            ull rd = dup2(rr[hb + 4 * i]);
            #pragma unroll
            for (int k = 0; k < 4; k++) {
                ull tmp = 0ull;
                fma2(tmp, o2[i][k], rd);
                o2[i][k] = tmp;
            }
        }
        #pragma unroll
        for (int s = 0; s < 16; s++) {
            ull pd[4];
            #pragma unroll
            for (int i = 0; i < 4; i++)
                pd[i] = dup2(pp[(hb + 4 * i) * 17 + s]);
            #pragma unroll
            for (int cc = 0; cc < 2; cc++) {
                ulonglong2 vv = *(const ulonglong2*)&kt[s * TSTR + vb + 64 * cc];
                #pragma unroll
                for (int i = 0; i < 4; i++) {
                    fma2(o2[i][2 * cc],     pd[i], vv.x);
                    fma2(o2[i][2 * cc + 1], pd[i], vv.y);
                }
            }
        }
        __syncthreads();   // b3: tile buffer free for reuse
        if (tl + 3 < 8) issueT(tl + 3);
    }

    // ---- epilogue
    if (t < 16) {
        g_bm[n * HH + t] = Mx[t];
        g_bs[n * HH + t] = Lx[t];
    }
    #pragma unroll
    for (int i = 0; i < 4; i++) {
        int h = hb + 4 * i;
        ulonglong2* dst = (ulonglong2*)(g_oacc + ((long)(n * HH + h)) * DVV);
        ulonglong2 v0; v0.x = o2[i][0]; v0.y = o2[i][1];
        ulonglong2 v1; v1.x = o2[i][2]; v1.y = o2[i][3];
        dst[vb]      = v0;
        dst[vb + 64] = v1;
    }
}

// ---------------- combine: group b owns blocks b*16..b*16+15 ----------------
__global__ __launch_bounds__(512) void mla_combine_kernel(float* __restrict__ out)
{
    const int b = blockIdx.x, h = blockIdx.y, t = threadIdx.x;
    __shared__ float w[16];

    if (t < 16) {
        float m = g_bm[(b * 16 + t) * HH + h];
        float gmax = m;
        #pragma unroll
        for (int o = 8; o >= 1; o >>= 1)
            gmax = fmaxf(gmax, __shfl_xor_sync(0xffffu, gmax, o, 16));
        float e = __expf(m - gmax);
        float gsum = g_bs[(b * 16 + t) * HH + h] * e;
        #pragma unroll
        for (int o = 8; o >= 1; o >>= 1)
            gsum += __shfl_xor_sync(0xffffu, gsum, o, 16);
        w[t] = e / gsum;
    }
    __syncthreads();

    float v[16];
    #pragma unroll
    for (int j = 0; j < 16; j++)
        v[j] = g_oacc[((long)((b * 16 + j) * HH + h)) * DVV + t];

    float acc = 0.f;
    #pragma unroll
    for (int j = 0; j < 16; j++)
        acc += w[j] * v[j];
    out[((long)(b * HH + h)) * DVV + t] = acc;
}

// -----------------------------------------------------------------------------
extern "C" void kernel_launch(void* const* d_in, const int* in_sizes, int n_in,
                              void* d_out, int out_size)
{
    const float* query        = (const float*)d_in[0];
    const float* key_cache    = (const float*)d_in[1];
    const float* block_bias   = (const float*)d_in[3];
    const int*   block_list   = (const int*)d_in[4];
    const int*   block_groups = (const int*)d_in[5];
    float* out = (float*)d_out;

    cudaFuncSetAttribute(mla_fused_kernel,
                         cudaFuncAttributeMaxDynamicSharedMemorySize, SMEM_BYTES);

    mla_fused_kernel<<<NBLK, 256, SMEM_BYTES>>>(
        query, key_cache, block_bias, block_list, block_groups);
    mla_combine_kernel<<<dim3(BQ, HH), 512>>>(out);
}

// round 10
// speedup vs baseline: 1.3469x; 1.3469x over previous
#include <cuda_runtime.h>
#include <math.h>
#include <cstdint>

// Problem constants
#define NBLK 512
#define BQ   32
#define HH   16
#define DD   576
#define DD4  144
#define DVV  512
#define BSS  128
#define QSCALE 0.07216878364870322f  // 192^-0.5

typedef unsigned long long ull;

// Scratch (device globals — no allocation allowed)
__device__ float g_oacc[NBLK * HH * DVV];
__device__ float g_bm[NBLK * HH];
__device__ float g_bs[NBLK * HH];

// ---------------- helpers ----------------
__device__ __forceinline__ uint32_t smem_u32(const void* p) {
    uint32_t a;
    asm("{ .reg .u64 t; cvta.to.shared.u64 t, %1; cvt.u32.u64 %0, t; }" : "=r"(a) : "l"(p));
    return a;
}
__device__ __forceinline__ void cp16(uint32_t dst, const void* src) {
    asm volatile("cp.async.cg.shared.global [%0], [%1], 16;" :: "r"(dst), "l"(src));
}
#define CP_COMMIT() asm volatile("cp.async.commit_group;" ::: "memory")
#define CP_WAIT(n)  asm volatile("cp.async.wait_group %0;" :: "n"(n) : "memory")

__device__ __forceinline__ void fma2(ull& d, ull a, ull b) {
    asm("fma.rn.f32x2 %0, %1, %2, %0;" : "+l"(d) : "l"(a), "l"(b));
}
__device__ __forceinline__ float lo_f(ull v) { return __uint_as_float((unsigned)v); }
__device__ __forceinline__ float hi_f(ull v) { return __uint_as_float((unsigned)(v >> 32)); }
__device__ __forceinline__ ull dup2(float v) {
    unsigned u = __float_as_uint(v);
    return ((ull)u << 32) | u;
}

// ---------------- SMEM layout (bytes) ----------------
// [0, 36864)      : K chunk double buffer: buf b at b*18432, 128 rows x 9 float4
//                   (reused in Pass C as V double buffer: buf b at b*16384,
//                    8 rows x 128 float4)
// [36864, 41472)  : Q chunk double buffer: buf b at QOFF + b*2304, 16 x 9 float4
// [41472, 49920)  : attn f32 [16][132]
#define KBUFB 18432
#define KSTR  9
#define QOFF  36864
#define QBUFB 2304
#define ATTOFF 41472
#define ATT_STRIDE 132
#define SMEM_BYTES 49920

#define CHUNK_F4 8    // 32 d-floats per chunk
#define NCH 18        // 576 / 32

__global__ __launch_bounds__(128, 4) void mla_block_kernel(
    const float* __restrict__ query,
    const float* __restrict__ key_cache,
    const float* __restrict__ block_bias,
    const int* __restrict__ block_list,
    const int* __restrict__ block_groups)
{
    extern __shared__ char smem[];
    const uint32_t sbase = smem_u32(smem);
    const int t = threadIdx.x;
    const int n = blockIdx.x;
    const int b = block_groups[n];
    const float4* kvb4 = (const float4*)(key_cache + (long)block_list[n] * (BSS * DD));
    const float4* q4 = (const float4*)query;
    float* attn = (float*)(smem + ATTOFF);

    // q loader mapping
    const int ls = t >> 3, lk = t & 7;

    // ---- Pass A issue: chunk c -> buffer c&1 (K 1024 f4 + Q 16 f4)
    auto issueA = [&](int c) {
        uint32_t kb = sbase + (unsigned)(c & 1) * KBUFB;
        #pragma unroll
        for (int j = 0; j < 8; j++) {
            int i = t + j * 128;
            int s = i >> 3, k = i & 7;
            cp16(kb + (unsigned)(s * KSTR + k) * 16,
                 kvb4 + (long)s * DD4 + c * CHUNK_F4 + k);
        }
        cp16(sbase + QOFF + (unsigned)(c & 1) * QBUFB + (unsigned)(ls * KSTR + lk) * 16,
             q4 + (long)(b * HH + ls) * DD4 + c * CHUNK_F4 + lk);
        CP_COMMIT();
    };
    // ---- Pass C issue: V tile tl -> buffer tl&1 (8 rows x 128 f4)
    auto issueC = [&](int tl) {
        uint32_t vbuf = sbase + (unsigned)(tl & 1) * 16384;
        #pragma unroll
        for (int j = 0; j < 8; j++) {
            int i = t + j * 128;
            int r = i >> 7, col = i & 127;
            cp16(vbuf + (unsigned)i * 16,
                 kvb4 + (long)(tl * 8 + r) * DD4 + col);
        }
        CP_COMMIT();
    };

    // ================= Pass A: attn = scale * q . kv =======================
    // thread tile: h = hq + 4*i, s = sq + 32*j  (conflict-free LDS)
    const int hq = t & 3;
    const int sq = t >> 2;   // 0..31

    ull acc2[4][4];
    #pragma unroll
    for (int i = 0; i < 4; i++)
        #pragma unroll
        for (int j = 0; j < 4; j++) acc2[i][j] = 0ull;

    issueA(0);
    issueA(1);

    for (int c = 0; c < NCH; c++) {
        if (c < NCH - 1) CP_WAIT(1); else CP_WAIT(0);
        __syncthreads();

        // Early V prefetch: during the last K chunk's compute (buf 1),
        // buffer 0 [0,16384) is free — start V tile 0 now.
        if (c == NCH - 1) issueC(0);

        const float4* kvs4 = (const float4*)(smem + (c & 1) * KBUFB);
        const float4* qc4  = (const float4*)(smem + QOFF + (c & 1) * QBUFB);

        #pragma unroll
        for (int k4 = 0; k4 < 8; k4++) {
            ull qp[4][2], kp[4][2];
            #pragma unroll
            for (int i = 0; i < 4; i++) {
                ulonglong2 qq = *(const ulonglong2*)&qc4[(hq + 4 * i) * KSTR + k4];
                qp[i][0] = qq.x; qp[i][1] = qq.y;
            }
            #pragma unroll
            for (int j = 0; j < 4; j++) {
                ulonglong2 kk = *(const ulonglong2*)&kvs4[(sq + 32 * j) * KSTR + k4];
                kp[j][0] = kk.x; kp[j][1] = kk.y;
            }
            #pragma unroll
            for (int i = 0; i < 4; i++)
                #pragma unroll
                for (int j = 0; j < 4; j++) {
                    fma2(acc2[i][j], qp[i][0], kp[j][0]);
                    fma2(acc2[i][j], qp[i][1], kp[j][1]);
                }
        }
        __syncthreads();
        if (c + 2 < NCH) issueA(c + 2);
    }

    // merge lo+hi, apply scale, add bias, write attn
    #pragma unroll
    for (int j = 0; j < 4; j++) {
        int s = sq + 32 * j;
        float bias = block_bias[n * BSS + s];
        #pragma unroll
        for (int i = 0; i < 4; i++) {
            int h = hq + 4 * i;
            attn[h * ATT_STRIDE + s] =
                (lo_f(acc2[i][j]) + hi_f(acc2[i][j])) * QSCALE + bias;
        }
    }
    __syncthreads();

    // V tile 1 (buffer 1 region free now: K buf1 fully consumed pre-barrier)
    issueC(1);

    // ================= Pass B: per-(n,h) softmax ===========================
    {
        int h = t >> 3, ln = t & 7;
        float m = -1e30f;
        #pragma unroll
        for (int r = 0; r < 16; r++)
            m = fmaxf(m, attn[h * ATT_STRIDE + ln + r * 8]);
        #pragma unroll
        for (int o = 4; o >= 1; o >>= 1)
            m = fmaxf(m, __shfl_xor_sync(0xffffffffu, m, o, 8));
        float l = 0.f;
        #pragma unroll
        for (int r = 0; r < 16; r++) {
            int idx = h * ATT_STRIDE + ln + r * 8;
            float p = __expf(attn[idx] - m);
            attn[idx] = p;
            l += p;
        }
        #pragma unroll
        for (int o = 4; o >= 1; o >>= 1)
            l += __shfl_xor_sync(0xffffffffu, l, o, 8);
        if (ln == 0) {
            g_bm[n * HH + h] = m;
            g_bs[n * HH + h] = l;
        }
    }

    // ================= Pass C: o = p @ v (f32x2, 16 tiles of 8 rows) =======
    const int hb = t & 3;
    const int vb = t >> 2;   // 0..31

    ull o2[4][8];
    #pragma unroll
    for (int i = 0; i < 4; i++)
        #pragma unroll
        for (int p = 0; p < 8; p++) o2[i][p] = 0ull;

    for (int tl = 0; tl < 16; tl++) {
        if (tl < 15) CP_WAIT(1); else CP_WAIT(0);
        __syncthreads();

        const float4* vs4 = (const float4*)(smem + (tl & 1) * 16384);
        #pragma unroll
        for (int s = 0; s < 8; s++) {
            ull pd[4];
            #pragma unroll
            for (int i = 0; i < 4; i++)
                pd[i] = dup2(attn[(hb + 4 * i) * ATT_STRIDE + tl * 8 + s]);
            #pragma unroll
            for (int cc = 0; cc < 4; cc++) {
                ulonglong2 vv = *(const ulonglong2*)&vs4[s * 128 + vb + cc * 32];
                #pragma unroll
                for (int i = 0; i < 4; i++) {
                    fma2(o2[i][2 * cc],     pd[i], vv.x);
                    fma2(o2[i][2 * cc + 1], pd[i], vv.y);
                }
            }
        }
        __syncthreads();
        if (tl + 2 < 16) issueC(tl + 2);
    }

    // store partials (each thread: 4 float4s per h at column vb + cc*32)
    #pragma unroll
    for (int i = 0; i < 4; i++) {
        int h = hb + 4 * i;
        ulonglong2* dst = (ulonglong2*)(g_oacc + ((long)(n * HH + h)) * DVV);
        #pragma unroll
        for (int cc = 0; cc < 4; cc++) {
            ulonglong2 v; v.x = o2[i][2 * cc]; v.y = o2[i][2 * cc + 1];
            dst[vb + cc * 32] = v;
        }
    }
}

// ---------------- combine: group b owns blocks b*16..b*16+15 ----------------
// 512 threads, thread owns one v-float; all 16 block loads in flight.
__global__ __launch_bounds__(512) void mla_combine_kernel(float* __restrict__ out)
{
    const int b = blockIdx.x, h = blockIdx.y, t = threadIdx.x;
    __shared__ float w[16];

    if (t < 16) {
        float m = g_bm[(b * 16 + t) * HH + h];
        float gmax = m;
        #pragma unroll
        for (int o = 8; o >= 1; o >>= 1)
            gmax = fmaxf(gmax, __shfl_xor_sync(0xffffu, gmax, o, 16));
        float e = __expf(m - gmax);
        float gsum = g_bs[(b * 16 + t) * HH + h] * e;
        #pragma unroll
        for (int o = 8; o >= 1; o >>= 1)
            gsum += __shfl_xor_sync(0xffffu, gsum, o, 16);
        w[t] = e / gsum;
    }
    __syncthreads();

    float v[16];
    #pragma unroll
    for (int j = 0; j < 16; j++)
        v[j] = g_oacc[((long)((b * 16 + j) * HH + h)) * DVV + t];

    float acc = 0.f;
    #pragma unroll
    for (int j = 0; j < 16; j++)
        acc += w[j] * v[j];
    out[((long)(b * HH + h)) * DVV + t] = acc;
}

// -----------------------------------------------------------------------------
extern "C" void kernel_launch(void* const* d_in, const int* in_sizes, int n_in,
                              void* d_out, int out_size)
{
    const float* query        = (const float*)d_in[0];
    const float* key_cache    = (const float*)d_in[1];
    const float* block_bias   = (const float*)d_in[3];
    const int*   block_list   = (const int*)d_in[4];
    const int*   block_groups = (const int*)d_in[5];
    float* out = (float*)d_out;

    cudaFuncSetAttribute(mla_block_kernel,
                         cudaFuncAttributeMaxDynamicSharedMemorySize, SMEM_BYTES);

    mla_block_kernel<<<NBLK, 128, SMEM_BYTES>>>(
        query, key_cache, block_bias, block_list, block_groups);
    mla_combine_kernel<<<dim3(BQ, HH), 512>>>(out);
}